// round 16
// baseline (speedup 1.0000x reference)
#include <cuda_runtime.h>
#include <cuda_fp16.h>
#include <cstdint>

#define B_ 4
#define S_ 2048
#define E_ 384
#define H_ 8
#define D_ 48
#define KP (S_ + 64)          // padded key pitch for compacted K/V

// ---------------- device scratch (no allocations allowed) ----------------
__device__ __align__(16) __half g_Xh[B_*S_*E_];     // fp16 input
__device__ __align__(16) __half g_Wh[4*E_*E_];      // fp16 Wq,Wk,Wv,Wo
__device__ __align__(16) __half g_Qc[B_*H_*S_*D_];  // fp16, log2e*scale folded
__device__ __align__(16) __half g_Kc[B_*H_*KP*D_];  // fp16 compacted
__device__ __align__(16) __half g_Vc[B_*H_*KP*D_];
__device__ __align__(16) __half g_attn[B_*S_*E_];   // fp16 normalized attention
__device__ __align__(16) float  g_Op[2*B_*S_*E_];   // fp32 un-normalized O partials
__device__ float g_lp[2*B_*H_*S_];                  // fp32 l partials
__device__ int g_idx[B_*S_];    // forward map: compacted p -> source row s (padded 0)
__device__ int g_nv[B_];

#define NEG_INF (__int_as_float(0xff800000))

// ---------------- helpers ----------------
__device__ __forceinline__ unsigned pk2(float x, float y) {
    __half2 h = __floats2half2_rn(x, y);
    return *(unsigned*)&h;
}
__device__ __forceinline__ unsigned h2ex2(unsigned x) {
    unsigned r; asm("ex2.approx.f16x2 %0, %1;" : "=r"(r) : "r"(x)); return r;
}
__device__ __forceinline__ unsigned smem_u32(const void* p) {
    return (unsigned)__cvta_generic_to_shared(p);
}
__device__ __forceinline__ void cpa16(unsigned dst, const void* src) {
    asm volatile("cp.async.cg.shared.global [%0], [%1], 16;" :: "r"(dst), "l"(src));
}
#define CP_COMMIT() asm volatile("cp.async.commit_group;")
#define CP_WAIT1()  asm volatile("cp.async.wait_group 1;")
// ---- programmatic dependent launch ----
__device__ __forceinline__ void gdc_wait() {
    asm volatile("griddepcontrol.wait;" ::: "memory");
}
__device__ __forceinline__ void gdc_launch_dependents() {
    asm volatile("griddepcontrol.launch_dependents;");
}
__device__ __forceinline__ void ldsm_x4(unsigned* r, unsigned addr) {
    asm volatile("ldmatrix.sync.aligned.m8n8.x4.shared.b16 {%0,%1,%2,%3}, [%4];"
        : "=r"(r[0]), "=r"(r[1]), "=r"(r[2]), "=r"(r[3]) : "r"(addr));
}
__device__ __forceinline__ void ldsm_x4_t(unsigned* r, unsigned addr) {
    asm volatile("ldmatrix.sync.aligned.m8n8.x4.trans.shared.b16 {%0,%1,%2,%3}, [%4];"
        : "=r"(r[0]), "=r"(r[1]), "=r"(r[2]), "=r"(r[3]) : "r"(addr));
}
__device__ __forceinline__ void mma_f16(float* c,
                                        unsigned a0, unsigned a1, unsigned a2, unsigned a3,
                                        unsigned b0, unsigned b1) {
    asm volatile(
        "mma.sync.aligned.m16n8k16.row.col.f32.f16.f16.f32 "
        "{%0,%1,%2,%3},{%4,%5,%6,%7},{%8,%9},{%0,%1,%2,%3};"
        : "+f"(c[0]), "+f"(c[1]), "+f"(c[2]), "+f"(c[3])
        : "r"(a0), "r"(a1), "r"(a2), "r"(a3), "r"(b0), "r"(b1));
}

// ---------------------------------------------------------------------------
// Kernel 0: fused fp32->fp16 convert (X + 4 weights) AND mask compaction.
// ---------------------------------------------------------------------------
#define X4_ ((B_*S_*E_)/4)   // 786432
#define W4_ ((E_*E_)/4)      // 36864
#define CVT_BLOCKS ((X4_ + 4*W4_) / 256)   // 3648

__global__ void prep_kernel(const float* __restrict__ X,
                            const float* __restrict__ Wq, const float* __restrict__ Wk,
                            const float* __restrict__ Wv, const float* __restrict__ Wo,
                            const void* __restrict__ maskp) {
    if (blockIdx.x < CVT_BLOCKS) {
        const int i4 = blockIdx.x * blockDim.x + threadIdx.x;
        float4 v; __half* dst;
        if (i4 < X4_) {
            v = ((const float4*)X)[i4];
            dst = g_Xh + (size_t)i4 * 4;
        } else {
            const int r = i4 - X4_;
            const int w = r / W4_;
            const int o = r % W4_;
            const float* Wsrc = (w == 0) ? Wq : (w == 1) ? Wk : (w == 2) ? Wv : Wo;
            v = ((const float4*)Wsrc)[o];
            dst = g_Wh + (size_t)w * E_ * E_ + (size_t)o * 4;
        }
        uint2 u; u.x = pk2(v.x, v.y); u.y = pk2(v.z, v.w);
        *(uint2*)dst = u;
        gdc_launch_dependents();
        return;
    }

    // ---- mask compaction, one block per batch ----
    const int b = blockIdx.x - CVT_BLOCKS;
    const int t = threadIdx.x;
    const int lane = t & 31;
    const int wid  = t >> 5;

    int okI = 1, okF = 1;
    const unsigned* mu = (const unsigned*)maskp;
    for (int i = t; i < 2048; i += 256) {
        unsigned v = mu[i];
        okI &= (v == 0u || v == 1u);
        okF &= (v == 0u || v == 0x3f800000u);
    }
    okI = __syncthreads_and(okI);
    okF = __syncthreads_and(okF);

    __shared__ int wsum[8];
    __shared__ unsigned char valid[S_];

    const int base = t * 8;
    int c = 0;
    #pragma unroll
    for (int u = 0; u < 8; ++u) {
        const int s = base + u;
        int m;
        if (okI)      m = (((const int*)maskp)[b*S_ + s] != 0);
        else if (okF) m = (((const unsigned*)maskp)[b*S_ + s] != 0u);
        else          m = (((const unsigned char*)maskp)[b*S_ + s] != 0);
        const int v = (m == 0);
        valid[s] = (unsigned char)v;
        c += v;
    }

    int inc = c;
    #pragma unroll
    for (int d = 1; d < 32; d <<= 1) {
        int v = __shfl_up_sync(0xffffffffu, inc, d);
        if (lane >= d) inc += v;
    }
    if (lane == 31) wsum[wid] = inc;
    __syncthreads();

    int woff = 0, total = 0;
    #pragma unroll
    for (int i = 0; i < 8; ++i) {
        woff  += (i < wid) ? wsum[i] : 0;
        total += wsum[i];
    }

    int off = woff + inc - c;
    #pragma unroll
    for (int u = 0; u < 8; ++u) {
        const int s = base + u;
        if (valid[s]) g_idx[b*S_ + off++] = s;
    }
    for (int p = t; p < S_; p += 256)
        if (p >= total) g_idx[b*S_ + p] = 0;
    if (t == 255) g_nv[b] = total;
    gdc_launch_dependents();
}

// ---------------------------------------------------------------------------
// GEMM config: BM=128, BN=64, BK=32, 128 threads (2x2 warps, tile 64x32),
// fp16 smem (stride 40 halves), cp.async 3-stage pipeline.
// ---------------------------------------------------------------------------
#define GST   40
#define A_STG (128*GST)
#define B_STG (64*GST)
#define NSTG  3
#define GEMM_SMEM (NSTG*(A_STG + B_STG)*2)   // 46080 bytes

// ---------------------------------------------------------------------------
// Kernel 2: fused QKV projection.  z=0: Q (scale folded); z=1/2: K/V only for
// compacted rows via gathered A loads; fully-dead blocks exit early.
// ---------------------------------------------------------------------------
__global__ void __launch_bounds__(128) qkv_gemm_kernel(
        const float* __restrict__ bq, const float* __restrict__ bk,
        const float* __restrict__ bv) {
    const int z = blockIdx.z;
    const __half* Wh = g_Wh + (size_t)z * E_ * E_;
    const float* bias = (z == 0) ? bq : (z == 1) ? bk : bv;

    extern __shared__ __half sg[];
    __half* As = sg;
    __half* Bs = sg + NSTG*A_STG;

    const int t    = threadIdx.x;
    const int warp = t >> 5;
    const int lane = t & 31;
    const int wm   = warp & 1;
    const int wn   = warp >> 1;
    const int m0   = blockIdx.x * 128;
    const int n0   = blockIdx.y * 64;
    const int gid  = lane >> 2;
    const int tig  = lane & 3;
    const int l15  = lane & 15;
    const int lk   = (lane >> 4) * 8;

    gdc_wait();   // producer: prep_kernel

    const int bb = m0 >> 11;
    const int p0 = m0 & (S_ - 1);
    if (z != 0) {
        if (p0 >= g_nv[bb]) {
            gdc_launch_dependents();
            return;
        }
    }

    const __half* rowp[4];
    const int rbase = t >> 2;
    #pragma unroll
    for (int i = 0; i < 4; ++i) {
        int src_row;
        if (z == 0) src_row = m0 + rbase + 32*i;
        else        src_row = bb*S_ + g_idx[bb*S_ + p0 + rbase + 32*i];
        rowp[i] = g_Xh + (size_t)src_row * E_;
    }

    float acc[4][4][4] = {};

    auto issue = [&](int s, int k0) {
        const int c16 = t & 3;
        #pragma unroll
        for (int i = 0; i < 4; ++i) {
            cpa16(smem_u32(As + s*A_STG + (rbase + 32*i)*GST + c16*8),
                  rowp[i] + k0 + c16*8);
        }
        #pragma unroll
        for (int i = 0; i < 2; ++i) {
            const int ch = t + i*128;
            const int row = ch >> 2, cc = ch & 3;
            cpa16(smem_u32(Bs + s*B_STG + row*GST + cc*8),
                  Wh + (size_t)(n0 + row)*E_ + k0 + cc*8);
        }
    };

    issue(0, 0);  CP_COMMIT();
    issue(1, 32); CP_COMMIT();

    int s = 0;
    #pragma unroll 1
    for (int it = 0; it < 12; ++it) {
        CP_WAIT1();
        __syncthreads();
        if (it + 2 < 12) issue((it + 2) % 3, (it + 2) * 32);
        CP_COMMIT();

        const unsigned abase = smem_u32(As + s*A_STG + (wm*64 + l15)*GST + lk);
        const unsigned bbase = smem_u32(Bs + s*B_STG + (wn*32 + l15)*GST + lk);
        #pragma unroll
        for (int c = 0; c < 2; ++c) {
            unsigned a[4][4];
            #pragma unroll
            for (int f = 0; f < 4; ++f) ldsm_x4(a[f], abase + f*16*GST*2 + c*32);
            #pragma unroll
            for (int bt = 0; bt < 2; ++bt) {
                unsigned br[4];
                ldsm_x4(br, bbase + bt*16*GST*2 + c*32);
                #pragma unroll
                for (int f = 0; f < 4; ++f) {
                    mma_f16(acc[f][2*bt],   a[f][0],a[f][1],a[f][2],a[f][3], br[0], br[2]);
                    mma_f16(acc[f][2*bt+1], a[f][0],a[f][1],a[f][2],a[f][3], br[1], br[3]);
                }
            }
        }
        s = (s + 1) % 3;
    }

    // 1/sqrt(48) * log2(e): scores come out of QK in log2 domain
    const float scale = 0.20823510f;

    #pragma unroll
    for (int mt = 0; mt < 4; ++mt) {
        #pragma unroll
        for (int nt = 0; nt < 4; ++nt) {
            const int n = n0 + wn*32 + nt*8 + 2*tig;
            const float bv0 = bias[n], bv1 = bias[n+1];
            const int h = n / D_, d = n % D_;
            #pragma unroll
            for (int half = 0; half < 2; ++half) {
                const int m = m0 + wm*64 + mt*16 + gid + half*8;
                const float v0 = acc[mt][nt][2*half]     + bv0;
                const float v1 = acc[mt][nt][2*half + 1] + bv1;
                if (z == 0) {
                    const int srow = m & (S_ - 1);
                    *(__half2*)&g_Qc[((size_t)(bb*H_ + h)*S_ + srow)*D_ + d] =
                        __floats2half2_rn(v0 * scale, v1 * scale);
                } else {
                    const int p = m & (S_ - 1);
                    __half* dst = (z == 1) ? g_Kc : g_Vc;
                    *(__half2*)&dst[((size_t)(bb*H_ + h)*KP + p)*D_ + d] =
                        __floats2half2_rn(v0, v1);
                }
            }
        }
    }
    gdc_launch_dependents();
}

// ---------------------------------------------------------------------------
// Kernel 3: SPLIT-K flash attention.  Grid (64, H, B): split = x>>5 handles
// key tiles ti = split, split+2, ...  No-max softmax makes partials additive:
// each split stores un-normalized fp32 (O, l); norm_kernel combines.
// ---------------------------------------------------------------------------
#define QST 56
#define KV_STG (64*QST)                 // halves per K (or V) stage
#define ATTN_SMEM (6*KV_STG*2)          // 43008 bytes

__global__ void __launch_bounds__(128, 5) attn_kernel() {
    extern __shared__ __half sm[];
    __half* KVb = sm;                   // stage s: K at s*2*KV_STG, V at +KV_STG
    __half* Qs  = KVb + 4*KV_STG;       // ALIAS: K stage 2 region (7168 B)

    const int b     = blockIdx.z;
    const int h     = blockIdx.y;
    const int qi    = blockIdx.x & 31;
    const int split = blockIdx.x >> 5;
    const int q0    = qi * 64;
    const int t  = threadIdx.x;
    const int warp = t >> 5;
    const int lane = t & 31;
    const int gid  = lane >> 2;
    const int tig  = lane & 3;
    const int l15  = lane & 15;
    const int lk   = (lane >> 4) * 8;

    const __half* Qg = g_Qc + (size_t)(b*H_ + h) * S_ * D_;
    const __half* Kg = g_Kc + (size_t)(b*H_ + h) * KP * D_;
    const __half* Vg = g_Vc + (size_t)(b*H_ + h) * KP * D_;

    // constant B-fragment of the "ones column": B[k][0] = 1 forall k
    const unsigned onesB = (gid == 0) ? 0x3C003C00u : 0u;

    gdc_wait();   // producer: qkv_gemm_kernel

    const int nv = g_nv[b];
    const int ntiles = (nv + 63) >> 6;
    const int ntl = (ntiles - split + 1) >> 1;   // my tiles: ti = split + 2*lt

    // load Q tile (64 x 48) into the stage-2 K alias
    #pragma unroll
    for (int r = 0; r < 3; ++r) {
        const int fi  = t + r * 128;       // 0..383
        const int row = fi / 6;
        const int c8  = (fi % 6) * 8;
        *(uint4*)&Qs[row * QST + c8] = *(const uint4*)&Qg[(size_t)(q0 + row)*D_ + c8];
    }

    auto issue_kv = [&](int s, int k0) {
        __half* Ks = KVb + s*2*KV_STG;
        __half* Vs = Ks + KV_STG;
        #pragma unroll
        for (int r = 0; r < 6; ++r) {
            const int flat = t + r * 128;            // 0..767
            const int c2   = (flat < 384) ? flat : flat - 384;
            const int row  = c2 / 6;
            const int c    = (c2 % 6) * 8;
            if (flat < 384)
                cpa16(smem_u32(Ks + row*QST + c), Kg + (size_t)(k0 + row)*D_ + c);
            else
                cpa16(smem_u32(Vs + row*QST + c), Vg + (size_t)(k0 + row)*D_ + c);
        }
    };

    if (ntl > 0) issue_kv(0, split*64);
    CP_COMMIT();
    if (ntl > 1) issue_kv(1, (split + 2)*64);
    CP_COMMIT();

    // hoist loop-invariant Q fragments into registers (before any stage-2 write)
    __syncthreads();
    unsigned qa[3][4];
    {
        const unsigned qb = smem_u32(Qs + (warp*16 + l15)*QST + lk);
        #pragma unroll
        for (int c = 0; c < 3; ++c) ldsm_x4(qa[c], qb + c*32);
    }

    // un-normalized accumulators; o6 collects row sums via the ones fragment
    float o[6][4];
    float o6[4] = {0.f, 0.f, 0.f, 0.f};
    #pragma unroll
    for (int dt = 0; dt < 6; ++dt)
        #pragma unroll
        for (int j = 0; j < 4; ++j) o[dt][j] = 0.f;

    #pragma unroll 1
    for (int lt = 0; lt < ntl; ++lt) {
        CP_WAIT1();
        __syncthreads();
        if (lt + 2 < ntl) issue_kv((lt + 2) % 3, (split + 2*(lt + 2))*64);
        CP_COMMIT();

        const int k0 = (split + 2*lt) * 64;
        const __half* Ks = KVb + (lt % 3)*2*KV_STG;
        const __half* Vs = Ks + KV_STG;

        // ---- scores (log2 domain): 16q x 64k per warp ----
        float sc[8][4];
        #pragma unroll
        for (int nt = 0; nt < 8; ++nt)
            #pragma unroll
            for (int j = 0; j < 4; ++j) sc[nt][j] = 0.f;

        const unsigned kb = smem_u32(Ks + l15*QST + lk);
        #pragma unroll
        for (int c = 0; c < 3; ++c) {
            #pragma unroll
            for (int kt = 0; kt < 4; ++kt) {
                unsigned br[4];
                ldsm_x4(br, kb + kt*16*QST*2 + c*32);
                mma_f16(sc[2*kt],   qa[c][0], qa[c][1], qa[c][2], qa[c][3], br[0], br[2]);
                mma_f16(sc[2*kt+1], qa[c][0], qa[c][1], qa[c][2], qa[c][3], br[1], br[3]);
            }
        }

        // ---- tail mask (exp2(-inf) = 0) ----
        if (k0 + 64 > nv) {
            #pragma unroll
            for (int nt = 0; nt < 8; ++nt) {
                const int c0 = k0 + nt*8 + 2*tig;
                if (c0     >= nv) { sc[nt][0] = NEG_INF; sc[nt][2] = NEG_INF; }
                if (c0 + 1 >= nv) { sc[nt][1] = NEG_INF; sc[nt][3] = NEG_INF; }
            }
        }

        // ---- p = exp2(score): pack to half2, then f16x2 MUFU exp ----
        unsigned pe[8][2];
        #pragma unroll
        for (int nt = 0; nt < 8; ++nt) {
            pe[nt][0] = h2ex2(pk2(sc[nt][0], sc[nt][1]));
            pe[nt][1] = h2ex2(pk2(sc[nt][2], sc[nt][3]));
        }

        // ---- O += P @ V ;  o6 += P @ ones (row-sum on tensor pipe) ----
        const unsigned vb = smem_u32(Vs + l15*QST + lk);
        #pragma unroll
        for (int c = 0; c < 4; ++c) {
            const unsigned a0 = pe[2*c][0];
            const unsigned a1 = pe[2*c][1];
            const unsigned a2 = pe[2*c+1][0];
            const unsigned a3 = pe[2*c+1][1];
            #pragma unroll
            for (int dg = 0; dg < 3; ++dg) {
                unsigned br[4];
                ldsm_x4_t(br, vb + c*16*QST*2 + dg*32);
                mma_f16(o[2*dg],   a0, a1, a2, a3, br[0], br[1]);
                mma_f16(o[2*dg+1], a0, a1, a2, a3, br[2], br[3]);
            }
            mma_f16(o6, a0, a1, a2, a3, onesB, onesB);
        }
    }

    // ---- epilogue: store un-normalized fp32 partials (O, l) ----
    float* Op = g_Op + (size_t)(split*B_ + b) * S_ * E_;
    const int r0 = warp * 16 + gid;
    const int qrow0 = q0 + r0;
    const int qrow1 = qrow0 + 8;
    #pragma unroll
    for (int dt = 0; dt < 6; ++dt) {
        const int dcol = h * D_ + dt*8 + 2*tig;
        *(float2*)&Op[(size_t)qrow0*E_ + dcol] = make_float2(o[dt][0], o[dt][1]);
        *(float2*)&Op[(size_t)qrow1*E_ + dcol] = make_float2(o[dt][2], o[dt][3]);
    }
    if (tig == 0) {
        float* lp = g_lp + ((size_t)(split*B_ + b)*H_ + h) * S_;
        lp[qrow0] = o6[0];
        lp[qrow1] = o6[2];
    }
    gdc_launch_dependents();
}

// ---------------------------------------------------------------------------
// Kernel 3b: combine split-K partials + normalize -> fp16 g_attn.
// Each thread handles 8 consecutive columns (never straddles a head).
// ---------------------------------------------------------------------------
#define NRM_BLOCKS ((B_*S_*E_) / (256*8))   // 1536

__global__ void norm_kernel() {
    gdc_wait();   // producer: attn_kernel
    const int idx = blockIdx.x * 256 + threadIdx.x;   // 0..393215
    const int row = idx / 48;            // E_/8 = 48 chunks per row
    const int c8  = (idx % 48) * 8;
    const int b   = row >> 11;
    const int srow = row & (S_ - 1);
    const int h   = c8 / D_;

    const float la = g_lp[((size_t)(0*B_ + b)*H_ + h)*S_ + srow];
    const float lb = g_lp[((size_t)(1*B_ + b)*H_ + h)*S_ + srow];
    const float il = 1.f / (la + lb);

    const float* A = g_Op + (size_t)row*E_ + c8;
    const float* Bp = A + (size_t)B_*S_*E_;
    float4 a0 = *(const float4*)&A[0],  a1 = *(const float4*)&A[4];
    float4 b0 = *(const float4*)&Bp[0], b1 = *(const float4*)&Bp[4];

    uint4 u;
    u.x = pk2((a0.x + b0.x)*il, (a0.y + b0.y)*il);
    u.y = pk2((a0.z + b0.z)*il, (a0.w + b0.w)*il);
    u.z = pk2((a1.x + b1.x)*il, (a1.y + b1.y)*il);
    u.w = pk2((a1.z + b1.z)*il, (a1.w + b1.w)*il);
    *(uint4*)&g_attn[(size_t)row*E_ + c8] = u;
    gdc_launch_dependents();
}

// ---------------------------------------------------------------------------
// Kernel 4: output projection.  out = attn @ Wo^T + bo (fp32 out).
// ---------------------------------------------------------------------------
__global__ void __launch_bounds__(128) out_gemm_kernel(
        const float* __restrict__ bo, float* __restrict__ out) {
    const __half* Wh = g_Wh + (size_t)3 * E_ * E_;

    extern __shared__ __half sg[];
    __half* As = sg;
    __half* Bs = sg + NSTG*A_STG;

    const int t    = threadIdx.x;
    const int warp = t >> 5;
    const int lane = t & 31;
    const int wm   = warp & 1;
    const int wn   = warp >> 1;
    const int m0   = blockIdx.x * 128;
    const int n0   = blockIdx.y * 64;
    const int gid  = lane >> 2;
    const int tig  = lane & 3;
    const int l15  = lane & 15;
    const int lk   = (lane >> 4) * 8;

    float acc[4][4][4] = {};

    auto issue = [&](int s, int k0) {
        #pragma unroll
        for (int i = 0; i < 4; ++i) {
            const int ch = t + i*128;
            const int row = ch >> 2, c16 = ch & 3;
            cpa16(smem_u32(As + s*A_STG + row*GST + c16*8),
                  g_attn + (size_t)(m0 + row)*E_ + k0 + c16*8);
        }
        #pragma unroll
        for (int i = 0; i < 2; ++i) {
            const int ch = t + i*128;
            const int row = ch >> 2, c16 = ch & 3;
            cpa16(smem_u32(Bs + s*B_STG + row*GST + c16*8),
                  Wh + (size_t)(n0 + row)*E_ + k0 + c16*8);
        }
    };

    gdc_wait();   // producer: norm_kernel (g_attn)

    issue(0, 0);  CP_COMMIT();
    issue(1, 32); CP_COMMIT();

    int s = 0;
    #pragma unroll 1
    for (int it = 0; it < 12; ++it) {
        CP_WAIT1();
        __syncthreads();
        if (it + 2 < 12) issue((it + 2) % 3, (it + 2) * 32);
        CP_COMMIT();

        const unsigned abase = smem_u32(As + s*A_STG + (wm*64 + l15)*GST + lk);
        const unsigned bbase = smem_u32(Bs + s*B_STG + (wn*32 + l15)*GST + lk);
        #pragma unroll
        for (int c = 0; c < 2; ++c) {
            unsigned a[4][4];
            #pragma unroll
            for (int f = 0; f < 4; ++f) ldsm_x4(a[f], abase + f*16*GST*2 + c*32);
            #pragma unroll
            for (int bt = 0; bt < 2; ++bt) {
                unsigned br[4];
                ldsm_x4(br, bbase + bt*16*GST*2 + c*32);
                #pragma unroll
                for (int f = 0; f < 4; ++f) {
                    mma_f16(acc[f][2*bt],   a[f][0],a[f][1],a[f][2],a[f][3], br[0], br[2]);
                    mma_f16(acc[f][2*bt+1], a[f][0],a[f][1],a[f][2],a[f][3], br[1], br[3]);
                }
            }
        }
        s = (s + 1) % 3;
    }

    #pragma unroll
    for (int mt = 0; mt < 4; ++mt) {
        #pragma unroll
        for (int nt = 0; nt < 4; ++nt) {
            const int m = m0 + wm*64 + mt*16 + gid;
            const int n = n0 + wn*32 + nt*8 + 2*tig;
            const float bv0 = bo[n], bv1 = bo[n+1];
            *(float2*)&out[(size_t)m * E_ + n] =
                make_float2(acc[mt][nt][0] + bv0, acc[mt][nt][1] + bv1);
            *(float2*)&out[(size_t)(m + 8) * E_ + n] =
                make_float2(acc[mt][nt][2] + bv0, acc[mt][nt][3] + bv1);
        }
    }
}

// ---------------------------------------------------------------------------
extern "C" void kernel_launch(void* const* d_in, const int* in_sizes, int n_in,
                              void* d_out, int out_size) {
    const float* X    = (const float*)d_in[0];
    const void*  mask = d_in[1];
    const float* Wq   = (const float*)d_in[2];
    const float* bq   = (const float*)d_in[3];
    const float* Wk   = (const float*)d_in[4];
    const float* bk   = (const float*)d_in[5];
    const float* Wv   = (const float*)d_in[6];
    const float* bv   = (const float*)d_in[7];
    const float* Wo   = (const float*)d_in[8];
    const float* bo   = (const float*)d_in[9];
    float* out = (float*)d_out;

    prep_kernel<<<CVT_BLOCKS + B_, 256>>>(X, Wq, Wk, Wv, Wo, mask);

    cudaLaunchAttribute pss[1];
    pss[0].id = cudaLaunchAttributeProgrammaticStreamSerialization;
    pss[0].val.programmaticStreamSerializationAllowed = 1;

    {
        cudaLaunchConfig_t cfg = {};
        cfg.gridDim  = dim3((B_*S_)/128, E_/64, 3);
        cfg.blockDim = dim3(128, 1, 1);
        cfg.dynamicSmemBytes = GEMM_SMEM;
        cfg.stream = 0;
        cfg.attrs = pss; cfg.numAttrs = 1;
        cudaLaunchKernelEx(&cfg, qkv_gemm_kernel, bq, bk, bv);
    }
    {
        cudaLaunchConfig_t cfg = {};
        cfg.gridDim  = dim3(64, H_, B_);     // x = qtile | split<<5
        cfg.blockDim = dim3(128, 1, 1);
        cfg.dynamicSmemBytes = ATTN_SMEM;
        cfg.stream = 0;
        cfg.attrs = pss; cfg.numAttrs = 1;
        cudaLaunchKernelEx(&cfg, attn_kernel);
    }
    {
        cudaLaunchConfig_t cfg = {};
        cfg.gridDim  = dim3(NRM_BLOCKS, 1, 1);
        cfg.blockDim = dim3(256, 1, 1);
        cfg.stream = 0;
        cfg.attrs = pss; cfg.numAttrs = 1;
        cudaLaunchKernelEx(&cfg, norm_kernel);
    }
    {
        cudaLaunchConfig_t cfg = {};
        cfg.gridDim  = dim3((B_*S_)/128, E_/64, 1);
        cfg.blockDim = dim3(128, 1, 1);
        cfg.dynamicSmemBytes = GEMM_SMEM;
        cfg.stream = 0;
        cfg.attrs = pss; cfg.numAttrs = 1;
        cudaLaunchKernelEx(&cfg, out_gemm_kernel, bo, out);
    }
}

// round 17
// speedup vs baseline: 1.0657x; 1.0657x over previous
#include <cuda_runtime.h>
#include <cuda_fp16.h>
#include <cstdint>

#define B_ 4
#define S_ 2048
#define E_ 384
#define H_ 8
#define D_ 48
#define KP (S_ + 64)          // padded key pitch for compacted K/V

// ---------------- device scratch (no allocations allowed) ----------------
__device__ __align__(16) __half g_Xh[B_*S_*E_];     // fp16 input
__device__ __align__(16) __half g_Wh[4*E_*E_];      // fp16 Wq,Wk,Wv,Wo
__device__ __align__(16) __half g_Qc[B_*H_*S_*D_];  // fp16, log2e*scale folded
__device__ __align__(16) __half g_Kc[B_*H_*KP*D_];  // fp16 compacted
__device__ __align__(16) __half g_Vc[B_*H_*KP*D_];
__device__ __align__(16) __half g_attn[B_*S_*E_];   // fp16 attention output
__device__ int g_idx[B_*S_];    // forward map: compacted p -> source row s (padded 0)
__device__ int g_nv[B_];

#define NEG_INF (__int_as_float(0xff800000))

// ---------------- helpers ----------------
__device__ __forceinline__ unsigned pk2(float x, float y) {
    __half2 h = __floats2half2_rn(x, y);
    return *(unsigned*)&h;
}
__device__ __forceinline__ unsigned h2ex2(unsigned x) {
    unsigned r; asm("ex2.approx.f16x2 %0, %1;" : "=r"(r) : "r"(x)); return r;
}
__device__ __forceinline__ unsigned smem_u32(const void* p) {
    return (unsigned)__cvta_generic_to_shared(p);
}
__device__ __forceinline__ void cpa16(unsigned dst, const void* src) {
    asm volatile("cp.async.cg.shared.global [%0], [%1], 16;" :: "r"(dst), "l"(src));
}
__device__ __forceinline__ void cpa16_ca(unsigned dst, const void* src) {
    asm volatile("cp.async.ca.shared.global [%0], [%1], 16;" :: "r"(dst), "l"(src));
}
#define CP_COMMIT() asm volatile("cp.async.commit_group;")
#define CP_WAIT1()  asm volatile("cp.async.wait_group 1;")
// ---- programmatic dependent launch ----
__device__ __forceinline__ void gdc_wait() {
    asm volatile("griddepcontrol.wait;" ::: "memory");
}
__device__ __forceinline__ void gdc_launch_dependents() {
    asm volatile("griddepcontrol.launch_dependents;");
}
__device__ __forceinline__ void ldsm_x4(unsigned* r, unsigned addr) {
    asm volatile("ldmatrix.sync.aligned.m8n8.x4.shared.b16 {%0,%1,%2,%3}, [%4];"
        : "=r"(r[0]), "=r"(r[1]), "=r"(r[2]), "=r"(r[3]) : "r"(addr));
}
__device__ __forceinline__ void ldsm_x4_t(unsigned* r, unsigned addr) {
    asm volatile("ldmatrix.sync.aligned.m8n8.x4.trans.shared.b16 {%0,%1,%2,%3}, [%4];"
        : "=r"(r[0]), "=r"(r[1]), "=r"(r[2]), "=r"(r[3]) : "r"(addr));
}
__device__ __forceinline__ void mma_f16(float* c,
                                        unsigned a0, unsigned a1, unsigned a2, unsigned a3,
                                        unsigned b0, unsigned b1) {
    asm volatile(
        "mma.sync.aligned.m16n8k16.row.col.f32.f16.f16.f32 "
        "{%0,%1,%2,%3},{%4,%5,%6,%7},{%8,%9},{%0,%1,%2,%3};"
        : "+f"(c[0]), "+f"(c[1]), "+f"(c[2]), "+f"(c[3])
        : "r"(a0), "r"(a1), "r"(a2), "r"(a3), "r"(b0), "r"(b1));
}

// ---------------------------------------------------------------------------
// Kernel 0: fused fp32->fp16 convert (X + 4 weights) AND mask compaction.
// ---------------------------------------------------------------------------
#define X4_ ((B_*S_*E_)/4)   // 786432
#define W4_ ((E_*E_)/4)      // 36864
#define CVT_BLOCKS ((X4_ + 4*W4_) / 256)   // 3648

__global__ void prep_kernel(const float* __restrict__ X,
                            const float* __restrict__ Wq, const float* __restrict__ Wk,
                            const float* __restrict__ Wv, const float* __restrict__ Wo,
                            const void* __restrict__ maskp) {
    if (blockIdx.x < CVT_BLOCKS) {
        const int i4 = blockIdx.x * blockDim.x + threadIdx.x;
        float4 v; __half* dst;
        if (i4 < X4_) {
            v = ((const float4*)X)[i4];
            dst = g_Xh + (size_t)i4 * 4;
        } else {
            const int r = i4 - X4_;
            const int w = r / W4_;
            const int o = r % W4_;
            const float* Wsrc = (w == 0) ? Wq : (w == 1) ? Wk : (w == 2) ? Wv : Wo;
            v = ((const float4*)Wsrc)[o];
            dst = g_Wh + (size_t)w * E_ * E_ + (size_t)o * 4;
        }
        uint2 u; u.x = pk2(v.x, v.y); u.y = pk2(v.z, v.w);
        *(uint2*)dst = u;
        gdc_launch_dependents();
        return;
    }

    // ---- mask compaction, one block per batch ----
    const int b = blockIdx.x - CVT_BLOCKS;
    const int t = threadIdx.x;
    const int lane = t & 31;
    const int wid  = t >> 5;

    int okI = 1, okF = 1;
    const unsigned* mu = (const unsigned*)maskp;
    for (int i = t; i < 2048; i += 256) {
        unsigned v = mu[i];
        okI &= (v == 0u || v == 1u);
        okF &= (v == 0u || v == 0x3f800000u);
    }
    okI = __syncthreads_and(okI);
    okF = __syncthreads_and(okF);

    __shared__ int wsum[8];
    __shared__ unsigned char valid[S_];

    const int base = t * 8;
    int c = 0;
    #pragma unroll
    for (int u = 0; u < 8; ++u) {
        const int s = base + u;
        int m;
        if (okI)      m = (((const int*)maskp)[b*S_ + s] != 0);
        else if (okF) m = (((const unsigned*)maskp)[b*S_ + s] != 0u);
        else          m = (((const unsigned char*)maskp)[b*S_ + s] != 0);
        const int v = (m == 0);
        valid[s] = (unsigned char)v;
        c += v;
    }

    int inc = c;
    #pragma unroll
    for (int d = 1; d < 32; d <<= 1) {
        int v = __shfl_up_sync(0xffffffffu, inc, d);
        if (lane >= d) inc += v;
    }
    if (lane == 31) wsum[wid] = inc;
    __syncthreads();

    int woff = 0, total = 0;
    #pragma unroll
    for (int i = 0; i < 8; ++i) {
        woff  += (i < wid) ? wsum[i] : 0;
        total += wsum[i];
    }

    int off = woff + inc - c;
    #pragma unroll
    for (int u = 0; u < 8; ++u) {
        const int s = base + u;
        if (valid[s]) g_idx[b*S_ + off++] = s;
    }
    for (int p = t; p < S_; p += 256)
        if (p >= total) g_idx[b*S_ + p] = 0;
    if (t == 255) g_nv[b] = total;
    gdc_launch_dependents();
}

// ---------------------------------------------------------------------------
// GEMM config: BM=128, BN=64, BK=32, 128 threads (2x2 warps, tile 64x32),
// fp16 smem (stride 40 halves), cp.async 3-stage pipeline.
// ---------------------------------------------------------------------------
#define GST   40
#define A_STG (128*GST)
#define B_STG (64*GST)
#define NSTG  3
#define GEMM_SMEM (NSTG*(A_STG + B_STG)*2)   // 46080 bytes

// ---------------------------------------------------------------------------
// Kernel 2: fused QKV projection.  z=0: Q (scale folded); z=1/2: K/V only for
// compacted rows via gathered A loads; fully-dead blocks exit early.
// ---------------------------------------------------------------------------
__global__ void __launch_bounds__(128) qkv_gemm_kernel(
        const float* __restrict__ bq, const float* __restrict__ bk,
        const float* __restrict__ bv) {
    const int z = blockIdx.z;
    const __half* Wh = g_Wh + (size_t)z * E_ * E_;
    const float* bias = (z == 0) ? bq : (z == 1) ? bk : bv;

    extern __shared__ __half sg[];
    __half* As = sg;
    __half* Bs = sg + NSTG*A_STG;

    const int t    = threadIdx.x;
    const int warp = t >> 5;
    const int lane = t & 31;
    const int wm   = warp & 1;
    const int wn   = warp >> 1;
    const int m0   = blockIdx.x * 128;
    const int n0   = blockIdx.y * 64;
    const int gid  = lane >> 2;
    const int tig  = lane & 3;
    const int l15  = lane & 15;
    const int lk   = (lane >> 4) * 8;

    gdc_wait();   // producer: prep_kernel

    const int bb = m0 >> 11;
    const int p0 = m0 & (S_ - 1);
    if (z != 0) {
        if (p0 >= g_nv[bb]) {
            gdc_launch_dependents();
            return;
        }
    }

    const __half* rowp[4];
    const int rbase = t >> 2;
    #pragma unroll
    for (int i = 0; i < 4; ++i) {
        int src_row;
        if (z == 0) src_row = m0 + rbase + 32*i;
        else        src_row = bb*S_ + g_idx[bb*S_ + p0 + rbase + 32*i];
        rowp[i] = g_Xh + (size_t)src_row * E_;
    }

    float acc[4][4][4] = {};

    auto issue = [&](int s, int k0) {
        const int c16 = t & 3;
        #pragma unroll
        for (int i = 0; i < 4; ++i) {
            cpa16(smem_u32(As + s*A_STG + (rbase + 32*i)*GST + c16*8),
                  rowp[i] + k0 + c16*8);
        }
        #pragma unroll
        for (int i = 0; i < 2; ++i) {
            const int ch = t + i*128;
            const int row = ch >> 2, cc = ch & 3;
            cpa16_ca(smem_u32(Bs + s*B_STG + row*GST + cc*8),
                     Wh + (size_t)(n0 + row)*E_ + k0 + cc*8);
        }
    };

    issue(0, 0);  CP_COMMIT();
    issue(1, 32); CP_COMMIT();

    int s = 0;
    #pragma unroll 1
    for (int it = 0; it < 12; ++it) {
        CP_WAIT1();
        __syncthreads();
        if (it + 2 < 12) issue((it + 2) % 3, (it + 2) * 32);
        CP_COMMIT();

        const unsigned abase = smem_u32(As + s*A_STG + (wm*64 + l15)*GST + lk);
        const unsigned bbase = smem_u32(Bs + s*B_STG + (wn*32 + l15)*GST + lk);
        #pragma unroll
        for (int c = 0; c < 2; ++c) {
            unsigned a[4][4];
            #pragma unroll
            for (int f = 0; f < 4; ++f) ldsm_x4(a[f], abase + f*16*GST*2 + c*32);
            #pragma unroll
            for (int bt = 0; bt < 2; ++bt) {
                unsigned br[4];
                ldsm_x4(br, bbase + bt*16*GST*2 + c*32);
                #pragma unroll
                for (int f = 0; f < 4; ++f) {
                    mma_f16(acc[f][2*bt],   a[f][0],a[f][1],a[f][2],a[f][3], br[0], br[2]);
                    mma_f16(acc[f][2*bt+1], a[f][0],a[f][1],a[f][2],a[f][3], br[1], br[3]);
                }
            }
        }
        s = (s + 1) % 3;
    }

    // 1/sqrt(48) * log2(e): scores come out of QK in log2 domain
    const float scale = 0.20823510f;

    #pragma unroll
    for (int mt = 0; mt < 4; ++mt) {
        #pragma unroll
        for (int nt = 0; nt < 4; ++nt) {
            const int n = n0 + wn*32 + nt*8 + 2*tig;
            const float bv0 = bias[n], bv1 = bias[n+1];
            const int h = n / D_, d = n % D_;
            #pragma unroll
            for (int half = 0; half < 2; ++half) {
                const int m = m0 + wm*64 + mt*16 + gid + half*8;
                const float v0 = acc[mt][nt][2*half]     + bv0;
                const float v1 = acc[mt][nt][2*half + 1] + bv1;
                if (z == 0) {
                    const int srow = m & (S_ - 1);
                    *(__half2*)&g_Qc[((size_t)(bb*H_ + h)*S_ + srow)*D_ + d] =
                        __floats2half2_rn(v0 * scale, v1 * scale);
                } else {
                    const int p = m & (S_ - 1);
                    __half* dst = (z == 1) ? g_Kc : g_Vc;
                    *(__half2*)&dst[((size_t)(bb*H_ + h)*KP + p)*D_ + d] =
                        __floats2half2_rn(v0, v1);
                }
            }
        }
    }
    gdc_launch_dependents();
}

// ---------------------------------------------------------------------------
// Kernel 3: flash attention.  BQ=64, 128 threads, private 3-stage K/V ring,
// Q staged in the stage-2 K alias, constant ones-B-fragment l-reduction,
// f16x2 exp.  smem 43008B -> 5 blocks/SM.
// ---------------------------------------------------------------------------
#define QST 56
#define KV_STG (64*QST)                 // halves per K (or V) stage
#define ATTN_SMEM (6*KV_STG*2)          // 43008 bytes

__global__ void __launch_bounds__(128, 5) attn_kernel() {
    extern __shared__ __half sm[];
    __half* KVb = sm;                   // stage s: K at s*2*KV_STG, V at +KV_STG
    __half* Qs  = KVb + 4*KV_STG;       // ALIAS: K stage 2 region (7168 B)

    const int b  = blockIdx.z;
    const int h  = blockIdx.y;
    const int q0 = blockIdx.x * 64;
    const int t  = threadIdx.x;
    const int warp = t >> 5;
    const int lane = t & 31;
    const int gid  = lane >> 2;
    const int tig  = lane & 3;
    const int l15  = lane & 15;
    const int lk   = (lane >> 4) * 8;

    const __half* Qg = g_Qc + (size_t)(b*H_ + h) * S_ * D_;
    const __half* Kg = g_Kc + (size_t)(b*H_ + h) * KP * D_;
    const __half* Vg = g_Vc + (size_t)(b*H_ + h) * KP * D_;

    // constant B-fragment of the "ones column": B[k][0] = 1 forall k
    const unsigned onesB = (gid == 0) ? 0x3C003C00u : 0u;

    gdc_wait();   // producer: qkv_gemm_kernel

    const int nv = g_nv[b];
    const int ntiles = (nv + 63) >> 6;

    // load Q tile (64 x 48) into the stage-2 K alias
    #pragma unroll
    for (int r = 0; r < 3; ++r) {
        const int fi  = t + r * 128;       // 0..383
        const int row = fi / 6;
        const int c8  = (fi % 6) * 8;
        *(uint4*)&Qs[row * QST + c8] = *(const uint4*)&Qg[(size_t)(q0 + row)*D_ + c8];
    }

    auto issue_kv = [&](int s, int k0) {
        __half* Ks = KVb + s*2*KV_STG;
        __half* Vs = Ks + KV_STG;
        #pragma unroll
        for (int r = 0; r < 6; ++r) {
            const int flat = t + r * 128;            // 0..767
            const int c2   = (flat < 384) ? flat : flat - 384;
            const int row  = c2 / 6;
            const int c    = (c2 % 6) * 8;
            if (flat < 384)
                cpa16(smem_u32(Ks + row*QST + c), Kg + (size_t)(k0 + row)*D_ + c);
            else
                cpa16(smem_u32(Vs + row*QST + c), Vg + (size_t)(k0 + row)*D_ + c);
        }
    };

    if (ntiles > 0) issue_kv(0, 0);
    CP_COMMIT();
    if (ntiles > 1) issue_kv(1, 64);
    CP_COMMIT();

    // hoist loop-invariant Q fragments into registers (before any stage-2 write)
    __syncthreads();
    unsigned qa[3][4];
    {
        const unsigned qb = smem_u32(Qs + (warp*16 + l15)*QST + lk);
        #pragma unroll
        for (int c = 0; c < 3; ++c) ldsm_x4(qa[c], qb + c*32);
    }

    // un-normalized accumulators; o6 collects row sums via the ones fragment
    float o[6][4];
    float o6[4] = {0.f, 0.f, 0.f, 0.f};
    #pragma unroll
    for (int dt = 0; dt < 6; ++dt)
        #pragma unroll
        for (int j = 0; j < 4; ++j) o[dt][j] = 0.f;

    #pragma unroll 1
    for (int ti = 0; ti < ntiles; ++ti) {
        CP_WAIT1();
        __syncthreads();
        if (ti + 2 < ntiles) issue_kv((ti + 2) % 3, (ti + 2) * 64);
        CP_COMMIT();

        const int k0 = ti * 64;
        const __half* Ks = KVb + (ti % 3)*2*KV_STG;
        const __half* Vs = Ks + KV_STG;

        // ---- scores (log2 domain): 16q x 64k per warp ----
        float sc[8][4];
        #pragma unroll
        for (int nt = 0; nt < 8; ++nt)
            #pragma unroll
            for (int j = 0; j < 4; ++j) sc[nt][j] = 0.f;

        const unsigned kb = smem_u32(Ks + l15*QST + lk);
        #pragma unroll
        for (int c = 0; c < 3; ++c) {
            #pragma unroll
            for (int kt = 0; kt < 4; ++kt) {
                unsigned br[4];
                ldsm_x4(br, kb + kt*16*QST*2 + c*32);
                mma_f16(sc[2*kt],   qa[c][0], qa[c][1], qa[c][2], qa[c][3], br[0], br[2]);
                mma_f16(sc[2*kt+1], qa[c][0], qa[c][1], qa[c][2], qa[c][3], br[1], br[3]);
            }
        }

        // ---- tail mask (exp2(-inf) = 0) ----
        if (k0 + 64 > nv) {
            #pragma unroll
            for (int nt = 0; nt < 8; ++nt) {
                const int c0 = k0 + nt*8 + 2*tig;
                if (c0     >= nv) { sc[nt][0] = NEG_INF; sc[nt][2] = NEG_INF; }
                if (c0 + 1 >= nv) { sc[nt][1] = NEG_INF; sc[nt][3] = NEG_INF; }
            }
        }

        // ---- p = exp2(score): pack to half2, then f16x2 MUFU exp ----
        unsigned pe[8][2];
        #pragma unroll
        for (int nt = 0; nt < 8; ++nt) {
            pe[nt][0] = h2ex2(pk2(sc[nt][0], sc[nt][1]));
            pe[nt][1] = h2ex2(pk2(sc[nt][2], sc[nt][3]));
        }

        // ---- O += P @ V ;  o6 += P @ ones (row-sum on tensor pipe) ----
        const unsigned vb = smem_u32(Vs + l15*QST + lk);
        #pragma unroll
        for (int c = 0; c < 4; ++c) {
            const unsigned a0 = pe[2*c][0];
            const unsigned a1 = pe[2*c][1];
            const unsigned a2 = pe[2*c+1][0];
            const unsigned a3 = pe[2*c+1][1];
            #pragma unroll
            for (int dg = 0; dg < 3; ++dg) {
                unsigned br[4];
                ldsm_x4_t(br, vb + c*16*QST*2 + dg*32);
                mma_f16(o[2*dg],   a0, a1, a2, a3, br[0], br[1]);
                mma_f16(o[2*dg+1], a0, a1, a2, a3, br[2], br[3]);
            }
            mma_f16(o6, a0, a1, a2, a3, onesB, onesB);
        }
    }

    // ---- harvest l from the ones fragment (col 0 -> tig==0 lane) ----
    const int src = lane & ~3;
    const float l0 = __shfl_sync(0xffffffffu, o6[0], src);
    const float l1 = __shfl_sync(0xffffffffu, o6[2], src);

    // ---- epilogue: normalize, write fp16 to g_attn [B,S,E] ----
    const float inv0 = 1.f / l0;
    const float inv1 = 1.f / l1;
    const int r0 = warp * 16 + gid;
    const int qrow0 = q0 + r0;
    const int qrow1 = qrow0 + 8;
    #pragma unroll
    for (int dt = 0; dt < 6; ++dt) {
        const int dcol = h * D_ + dt*8 + 2*tig;
        *(__half2*)&g_attn[(size_t)(b*S_ + qrow0)*E_ + dcol] =
            __floats2half2_rn(o[dt][0] * inv0, o[dt][1] * inv0);
        *(__half2*)&g_attn[(size_t)(b*S_ + qrow1)*E_ + dcol] =
            __floats2half2_rn(o[dt][2] * inv1, o[dt][3] * inv1);
    }
    gdc_launch_dependents();
}

// ---------------------------------------------------------------------------
// Kernel 4: output projection.  out = attn @ Wo^T + bo (fp32 out).
// ---------------------------------------------------------------------------
__global__ void __launch_bounds__(128) out_gemm_kernel(
        const float* __restrict__ bo, float* __restrict__ out) {
    const __half* Wh = g_Wh + (size_t)3 * E_ * E_;

    extern __shared__ __half sg[];
    __half* As = sg;
    __half* Bs = sg + NSTG*A_STG;

    const int t    = threadIdx.x;
    const int warp = t >> 5;
    const int lane = t & 31;
    const int wm   = warp & 1;
    const int wn   = warp >> 1;
    const int m0   = blockIdx.x * 128;
    const int n0   = blockIdx.y * 64;
    const int gid  = lane >> 2;
    const int tig  = lane & 3;
    const int l15  = lane & 15;
    const int lk   = (lane >> 4) * 8;

    float acc[4][4][4] = {};

    auto issue = [&](int s, int k0) {
        #pragma unroll
        for (int i = 0; i < 4; ++i) {
            const int ch = t + i*128;
            const int row = ch >> 2, c16 = ch & 3;
            cpa16(smem_u32(As + s*A_STG + row*GST + c16*8),
                  g_attn + (size_t)(m0 + row)*E_ + k0 + c16*8);
        }
        #pragma unroll
        for (int i = 0; i < 2; ++i) {
            const int ch = t + i*128;
            const int row = ch >> 2, c16 = ch & 3;
            cpa16_ca(smem_u32(Bs + s*B_STG + row*GST + c16*8),
                     Wh + (size_t)(n0 + row)*E_ + k0 + c16*8);
        }
    };

    gdc_wait();   // producer: attn_kernel (g_attn)

    issue(0, 0);  CP_COMMIT();
    issue(1, 32); CP_COMMIT();

    int s = 0;
    #pragma unroll 1
    for (int it = 0; it < 12; ++it) {
        CP_WAIT1();
        __syncthreads();
        if (it + 2 < 12) issue((it + 2) % 3, (it + 2) * 32);
        CP_COMMIT();

        const unsigned abase = smem_u32(As + s*A_STG + (wm*64 + l15)*GST + lk);
        const unsigned bbase = smem_u32(Bs + s*B_STG + (wn*32 + l15)*GST + lk);
        #pragma unroll
        for (int c = 0; c < 2; ++c) {
            unsigned a[4][4];
            #pragma unroll
            for (int f = 0; f < 4; ++f) ldsm_x4(a[f], abase + f*16*GST*2 + c*32);
            #pragma unroll
            for (int bt = 0; bt < 2; ++bt) {
                unsigned br[4];
                ldsm_x4(br, bbase + bt*16*GST*2 + c*32);
                #pragma unroll
                for (int f = 0; f < 4; ++f) {
                    mma_f16(acc[f][2*bt],   a[f][0],a[f][1],a[f][2],a[f][3], br[0], br[2]);
                    mma_f16(acc[f][2*bt+1], a[f][0],a[f][1],a[f][2],a[f][3], br[1], br[3]);
                }
            }
        }
        s = (s + 1) % 3;
    }

    #pragma unroll
    for (int mt = 0; mt < 4; ++mt) {
        #pragma unroll
        for (int nt = 0; nt < 4; ++nt) {
            const int m = m0 + wm*64 + mt*16 + gid;
            const int n = n0 + wn*32 + nt*8 + 2*tig;
            const float bv0 = bo[n], bv1 = bo[n+1];
            *(float2*)&out[(size_t)m * E_ + n] =
                make_float2(acc[mt][nt][0] + bv0, acc[mt][nt][1] + bv1);
            *(float2*)&out[(size_t)(m + 8) * E_ + n] =
                make_float2(acc[mt][nt][2] + bv0, acc[mt][nt][3] + bv1);
        }
    }
}

// ---------------------------------------------------------------------------
extern "C" void kernel_launch(void* const* d_in, const int* in_sizes, int n_in,
                              void* d_out, int out_size) {
    const float* X    = (const float*)d_in[0];
    const void*  mask = d_in[1];
    const float* Wq   = (const float*)d_in[2];
    const float* bq   = (const float*)d_in[3];
    const float* Wk   = (const float*)d_in[4];
    const float* bk   = (const float*)d_in[5];
    const float* Wv   = (const float*)d_in[6];
    const float* bv   = (const float*)d_in[7];
    const float* Wo   = (const float*)d_in[8];
    const float* bo   = (const float*)d_in[9];
    float* out = (float*)d_out;

    prep_kernel<<<CVT_BLOCKS + B_, 256>>>(X, Wq, Wk, Wv, Wo, mask);

    cudaLaunchAttribute pss[1];
    pss[0].id = cudaLaunchAttributeProgrammaticStreamSerialization;
    pss[0].val.programmaticStreamSerializationAllowed = 1;

    {
        cudaLaunchConfig_t cfg = {};
        cfg.gridDim  = dim3((B_*S_)/128, E_/64, 3);
        cfg.blockDim = dim3(128, 1, 1);
        cfg.dynamicSmemBytes = GEMM_SMEM;
        cfg.stream = 0;
        cfg.attrs = pss; cfg.numAttrs = 1;
        cudaLaunchKernelEx(&cfg, qkv_gemm_kernel, bq, bk, bv);
    }
    {
        cudaLaunchConfig_t cfg = {};
        cfg.gridDim  = dim3(S_/64, H_, B_);
        cfg.blockDim = dim3(128, 1, 1);
        cfg.dynamicSmemBytes = ATTN_SMEM;
        cfg.stream = 0;
        cfg.attrs = pss; cfg.numAttrs = 1;
        cudaLaunchKernelEx(&cfg, attn_kernel);
    }
    {
        cudaLaunchConfig_t cfg = {};
        cfg.gridDim  = dim3((B_*S_)/128, E_/64, 1);
        cfg.blockDim = dim3(128, 1, 1);
        cfg.dynamicSmemBytes = GEMM_SMEM;
        cfg.stream = 0;
        cfg.attrs = pss; cfg.numAttrs = 1;
        cudaLaunchKernelEx(&cfg, out_gemm_kernel, bo, out);
    }
}